// round 1
// baseline (speedup 1.0000x reference)
#include <cuda_runtime.h>
#include <mma.h>
#include <cmath>

using namespace nvcuda;

// Problem constants (fixed by the reference)
constexpr int NE   = 8;     // experts
constexpr int DMODEL = 1024;
constexpr int FF   = 2048;
constexpr int NTOK = 8192;  // 4 * 2048
constexpr int TOPK = 2;
constexpr int CAP  = 8192;  // per-expert worst-case capacity (each token -> 2 distinct experts)

// Scratch (module-load allocated; allowed)
__device__ float g_H[(long long)NE * CAP * FF];   // hidden activations, 512 MB capacity
__device__ int   g_tok[NE * CAP];
__device__ float g_gate[NE * CAP];
__device__ int   g_cnt[NE];

// ---------------------------------------------------------------------------
// Kernel 0: zero output + counters
// ---------------------------------------------------------------------------
__global__ void zero_kernel(float* __restrict__ out, int n4) {
    int i = blockIdx.x * blockDim.x + threadIdx.x;
    if (i < n4) {
        float4 z = make_float4(0.f, 0.f, 0.f, 0.f);
        reinterpret_cast<float4*>(out)[i] = z;
    }
    if (i < NE) g_cnt[i] = 0;
}

// ---------------------------------------------------------------------------
// Kernel 1: router (one warp per token) + scatter into per-expert segments
// ---------------------------------------------------------------------------
__global__ void router_kernel(const float* __restrict__ x,
                              const float* __restrict__ Wr) {
    int warp = (blockIdx.x * blockDim.x + threadIdx.x) >> 5;
    int lane = threadIdx.x & 31;
    if (warp >= NTOK) return;

    const float* xr = x + (size_t)warp * DMODEL;
    float acc[NE];
#pragma unroll
    for (int e = 0; e < NE; e++) acc[e] = 0.f;

#pragma unroll 4
    for (int i = 0; i < DMODEL / 32; i++) {
        int d = i * 32 + lane;
        float xv = xr[d];
#pragma unroll
        for (int e = 0; e < NE; e++) acc[e] += xv * Wr[e * DMODEL + d];
    }
#pragma unroll
    for (int e = 0; e < NE; e++) {
#pragma unroll
        for (int o = 16; o > 0; o >>= 1)
            acc[e] += __shfl_xor_sync(0xffffffffu, acc[e], o);
    }

    if (lane == 0) {
        float m = acc[0];
#pragma unroll
        for (int e = 1; e < NE; e++) m = fmaxf(m, acc[e]);
        float p[NE];
#pragma unroll
        for (int e = 0; e < NE; e++) p[e] = expf(acc[e] - m);

        // top-2 (strict > keeps lowest index on ties, matching lax.top_k)
        int i1 = 0;
#pragma unroll
        for (int e = 1; e < NE; e++) if (p[e] > p[i1]) i1 = e;
        int i2 = (i1 == 0) ? 1 : 0;
#pragma unroll
        for (int e = 0; e < NE; e++) {
            if (e == i1) continue;
            if (p[e] > p[i2]) i2 = e;
        }
        float g1 = p[i1], g2 = p[i2];
        float inv = 1.f / (g1 + g2);   // softmax denom cancels in the renorm
        g1 *= inv; g2 *= inv;

        int pos1 = atomicAdd(&g_cnt[i1], 1);
        g_tok[i1 * CAP + pos1]  = warp;
        g_gate[i1 * CAP + pos1] = g1;
        int pos2 = atomicAdd(&g_cnt[i2], 1);
        g_tok[i2 * CAP + pos2]  = warp;
        g_gate[i2 * CAP + pos2] = g2;
    }
}

// ---------------------------------------------------------------------------
// Grouped GEMMs: 128x64 block tile, BK=16, 8 warps, wmma m16n16k8 tf32
// ---------------------------------------------------------------------------
constexpr int BM = 128;
constexpr int BN = 64;
constexpr int BK = 16;
constexpr int BSTRIDE = 72;   // padded B tile stride (32B-aligned fragment ptrs)

__device__ __forceinline__ float gelu_exact(float v) {
    return 0.5f * v * (1.0f + erff(v * 0.70710678118654752f));
}

// GEMM1: H[e][m][f] = gelu( gather(x)[m] . W1[e][:,f] + b1[e][f] )
__global__ __launch_bounds__(256) void ffn1_kernel(const float* __restrict__ x,
                                                   const float* __restrict__ W1,
                                                   const float* __restrict__ b1) {
    int e   = blockIdx.z;
    int cnt = g_cnt[e];
    int m0  = blockIdx.y * BM;
    if (m0 >= cnt) return;
    int f0  = blockIdx.x * BN;

    __shared__ float As[BM * BK];        // 8 KB (reused as epilogue stage)
    __shared__ float Bs[BK * BSTRIDE];   // 4.5 KB

    int tid    = threadIdx.x;
    int warpId = tid >> 5;
    int lane   = tid & 31;

    // A loading map: 2 float4 per thread, fixed rows
    int rowA = tid >> 2;            // 0..63
    int colA = (tid & 3) * 4;       // 0,4,8,12
    int r0 = m0 + rowA, r1 = m0 + 64 + rowA;
    const float* aptr0 = (r0 < cnt) ? x + (size_t)g_tok[e * CAP + r0] * DMODEL : nullptr;
    const float* aptr1 = (r1 < cnt) ? x + (size_t)g_tok[e * CAP + r1] * DMODEL : nullptr;

    // B loading map: 1 float4 per thread
    int rB  = tid >> 4;             // 0..15
    int cB4 = (tid & 15) * 4;       // 0..60

    wmma::fragment<wmma::matrix_a, 16, 16, 8, wmma::precision::tf32, wmma::row_major> af[2];
    wmma::fragment<wmma::matrix_b, 16, 16, 8, wmma::precision::tf32, wmma::row_major> bf[2];
    wmma::fragment<wmma::accumulator, 16, 16, 8, float> cf[2][2];
#pragma unroll
    for (int i = 0; i < 2; i++)
#pragma unroll
        for (int j = 0; j < 2; j++) wmma::fill_fragment(cf[i][j], 0.f);

    int wm = warpId >> 1;   // 0..3
    int wn = warpId & 1;    // 0..1

    const float4 z4 = make_float4(0.f, 0.f, 0.f, 0.f);
    for (int k0 = 0; k0 < DMODEL; k0 += BK) {
        float4 va = aptr0 ? *reinterpret_cast<const float4*>(aptr0 + k0 + colA) : z4;
        float4 vb = aptr1 ? *reinterpret_cast<const float4*>(aptr1 + k0 + colA) : z4;
        *reinterpret_cast<float4*>(&As[rowA * BK + colA]) = va;
        *reinterpret_cast<float4*>(&As[(64 + rowA) * BK + colA]) = vb;
        float4 w = *reinterpret_cast<const float4*>(
            W1 + ((size_t)e * DMODEL + k0 + rB) * FF + f0 + cB4);
        *reinterpret_cast<float4*>(&Bs[rB * BSTRIDE + cB4]) = w;
        __syncthreads();

#pragma unroll
        for (int kk = 0; kk < BK; kk += 8) {
#pragma unroll
            for (int i = 0; i < 2; i++) {
                wmma::load_matrix_sync(af[i], &As[(wm * 32 + i * 16) * BK + kk], BK);
#pragma unroll
                for (int t = 0; t < af[i].num_elements; t++)
                    af[i].x[t] = wmma::__float_to_tf32(af[i].x[t]);
            }
#pragma unroll
            for (int j = 0; j < 2; j++) {
                wmma::load_matrix_sync(bf[j], &Bs[kk * BSTRIDE + wn * 32 + j * 16], BSTRIDE);
#pragma unroll
                for (int t = 0; t < bf[j].num_elements; t++)
                    bf[j].x[t] = wmma::__float_to_tf32(bf[j].x[t]);
            }
#pragma unroll
            for (int i = 0; i < 2; i++)
#pragma unroll
                for (int j = 0; j < 2; j++)
                    wmma::mma_sync(cf[i][j], af[i], bf[j], cf[i][j]);
        }
        __syncthreads();
    }

    // Epilogue: bias + exact GELU, store to H (stage through smem, reuse As)
    float* stage = As + warpId * 256;
#pragma unroll
    for (int i = 0; i < 2; i++) {
#pragma unroll
        for (int j = 0; j < 2; j++) {
            wmma::store_matrix_sync(stage, cf[i][j], 16, wmma::mem_row_major);
            __syncwarp();
            int gm_base = m0 + wm * 32 + i * 16;
            int gf_base = f0 + wn * 32 + j * 16;
#pragma unroll
            for (int q = 0; q < 8; q++) {
                int idx = lane * 8 + q;
                int lr = idx >> 4, lc = idx & 15;
                int gm = gm_base + lr;
                if (gm < cnt) {
                    int gf = gf_base + lc;
                    float v = stage[idx] + b1[e * FF + gf];
                    g_H[((size_t)e * CAP + gm) * FF + gf] = gelu_exact(v);
                }
            }
            __syncwarp();
        }
    }
}

// GEMM2: out[tok] += gate * ( H[e][m] . W2[e][:,d] + b2[e][d] )
__global__ __launch_bounds__(256) void ffn2_kernel(const float* __restrict__ W2,
                                                   const float* __restrict__ b2,
                                                   float* __restrict__ out) {
    int e   = blockIdx.z;
    int cnt = g_cnt[e];
    int m0  = blockIdx.y * BM;
    if (m0 >= cnt) return;
    int d0  = blockIdx.x * BN;

    __shared__ float As[BM * BK];
    __shared__ float Bs[BK * BSTRIDE];

    int tid    = threadIdx.x;
    int warpId = tid >> 5;
    int lane   = tid & 31;

    int rowA = tid >> 2;
    int colA = (tid & 3) * 4;
    const float* aptr0 = g_H + ((size_t)e * CAP + m0 + rowA) * FF;        // rows >= cnt read
    const float* aptr1 = g_H + ((size_t)e * CAP + m0 + 64 + rowA) * FF;   // stale-but-finite data

    int rB  = tid >> 4;
    int cB4 = (tid & 15) * 4;

    wmma::fragment<wmma::matrix_a, 16, 16, 8, wmma::precision::tf32, wmma::row_major> af[2];
    wmma::fragment<wmma::matrix_b, 16, 16, 8, wmma::precision::tf32, wmma::row_major> bf[2];
    wmma::fragment<wmma::accumulator, 16, 16, 8, float> cf[2][2];
#pragma unroll
    for (int i = 0; i < 2; i++)
#pragma unroll
        for (int j = 0; j < 2; j++) wmma::fill_fragment(cf[i][j], 0.f);

    int wm = warpId >> 1;
    int wn = warpId & 1;

    for (int k0 = 0; k0 < FF; k0 += BK) {
        float4 va = *reinterpret_cast<const float4*>(aptr0 + k0 + colA);
        float4 vb = *reinterpret_cast<const float4*>(aptr1 + k0 + colA);
        *reinterpret_cast<float4*>(&As[rowA * BK + colA]) = va;
        *reinterpret_cast<float4*>(&As[(64 + rowA) * BK + colA]) = vb;
        float4 w = *reinterpret_cast<const float4*>(
            W2 + ((size_t)e * FF + k0 + rB) * DMODEL + d0 + cB4);
        *reinterpret_cast<float4*>(&Bs[rB * BSTRIDE + cB4]) = w;
        __syncthreads();

#pragma unroll
        for (int kk = 0; kk < BK; kk += 8) {
#pragma unroll
            for (int i = 0; i < 2; i++) {
                wmma::load_matrix_sync(af[i], &As[(wm * 32 + i * 16) * BK + kk], BK);
#pragma unroll
                for (int t = 0; t < af[i].num_elements; t++)
                    af[i].x[t] = wmma::__float_to_tf32(af[i].x[t]);
            }
#pragma unroll
            for (int j = 0; j < 2; j++) {
                wmma::load_matrix_sync(bf[j], &Bs[kk * BSTRIDE + wn * 32 + j * 16], BSTRIDE);
#pragma unroll
                for (int t = 0; t < bf[j].num_elements; t++)
                    bf[j].x[t] = wmma::__float_to_tf32(bf[j].x[t]);
            }
#pragma unroll
            for (int i = 0; i < 2; i++)
#pragma unroll
                for (int j = 0; j < 2; j++)
                    wmma::mma_sync(cf[i][j], af[i], bf[j], cf[i][j]);
        }
        __syncthreads();
    }

    // Epilogue: bias + gate-scaled atomic combine into out
    float* stage = As + warpId * 256;
#pragma unroll
    for (int i = 0; i < 2; i++) {
#pragma unroll
        for (int j = 0; j < 2; j++) {
            wmma::store_matrix_sync(stage, cf[i][j], 16, wmma::mem_row_major);
            __syncwarp();
            int gm_base = m0 + wm * 32 + i * 16;
            int gd_base = d0 + wn * 32 + j * 16;
#pragma unroll
            for (int q = 0; q < 8; q++) {
                int idx = lane * 8 + q;
                int lr = idx >> 4, lc = idx & 15;
                int gm = gm_base + lr;
                if (gm < cnt) {
                    int tok    = g_tok[e * CAP + gm];
                    float gate = g_gate[e * CAP + gm];
                    int gd = gd_base + lc;
                    float v = stage[idx] + b2[e * DMODEL + gd];
                    atomicAdd(&out[(size_t)tok * DMODEL + gd], gate * v);
                }
            }
            __syncwarp();
        }
    }
}

// ---------------------------------------------------------------------------
extern "C" void kernel_launch(void* const* d_in, const int* in_sizes, int n_in,
                              void* d_out, int out_size) {
    const float* x  = (const float*)d_in[0];
    const float* Wr = (const float*)d_in[1];
    const float* W1 = (const float*)d_in[2];
    const float* b1 = (const float*)d_in[3];
    const float* W2 = (const float*)d_in[4];
    const float* b2 = (const float*)d_in[5];
    float* out = (float*)d_out;

    int n4 = NTOK * DMODEL / 4;
    zero_kernel<<<(n4 + 255) / 256, 256>>>(out, n4);
    router_kernel<<<(NTOK * 32) / 256, 256>>>(x, Wr);

    dim3 g1(FF / BN, CAP / BM, NE);   // (32, 64, 8)
    ffn1_kernel<<<g1, 256>>>(x, W1, b1);

    dim3 g2(DMODEL / BN, CAP / BM, NE);  // (16, 64, 8)
    ffn2_kernel<<<g2, 256>>>(W2, b2, out);
}

// round 5
// speedup vs baseline: 1.0386x; 1.0386x over previous
#include <cuda_runtime.h>
#include <mma.h>
#include <cstdint>
#include <cmath>

using namespace nvcuda;

// ============================ problem constants ============================
constexpr int NE     = 8;
constexpr int DMODEL = 1024;
constexpr int FF     = 2048;
constexpr int NTOK   = 8192;   // 4*2048
constexpr int CAP    = 8192;   // per-expert worst-case rows

// ============================ scratch (module-load) ========================
__device__ float g_xr [(size_t)NTOK * DMODEL];        // tf32-rounded x       (32 MB)
__device__ float g_W1r[(size_t)NE * DMODEL * FF];     // tf32-rounded W1      (64 MB)
__device__ float g_W2r[(size_t)NE * FF * DMODEL];     // tf32-rounded W2      (64 MB)
__device__ float g_H  [(size_t)NE * CAP * FF];        // hidden (tf32-rounded)(512 MB)
__device__ float g_Y  [(size_t)NE * CAP * DMODEL];    // expert outputs       (256 MB)
__device__ int   g_tok  [NE * CAP];
__device__ int   g_cnt  [NE];
__device__ int   g_oslot[NTOK * 2];                   // token -> slot in g_Y
__device__ float g_ogate[NTOK * 2];                   // token -> gate

// ============================ helpers ======================================
__device__ __forceinline__ uint32_t smem_u32(const void* p) {
    uint32_t a;
    asm("{ .reg .u64 t; cvta.to.shared.u64 t, %1; cvt.u32.u64 %0, t; }" : "=r"(a) : "l"(p));
    return a;
}
__device__ __forceinline__ float tf32r(float x) {
    uint32_t u;
    asm("cvt.rna.tf32.f32 %0, %1;" : "=r"(u) : "f"(x));
    return __uint_as_float(u);
}
#define CP_ASYNC16(dst, src) \
    asm volatile("cp.async.cg.shared.global [%0], [%1], 16;" :: "r"(dst), "l"(src) : "memory")
#define CP_COMMIT()  asm volatile("cp.async.commit_group;" ::: "memory")

__device__ __forceinline__ float gelu_exact(float v) {
    return 0.5f * v * (1.0f + erff(v * 0.70710678118654752f));
}

// ============================ GEMM config ==================================
constexpr int BM = 128;
constexpr int BN = 256;
constexpr int BK = 32;
constexpr int THREADS = 256;
constexpr int ASTR = 36;                 // A smem stride (floats), 144B mult-of-16
constexpr int BSTR = 260;                // B / C smem stride (floats), 1040B
constexpr int A_F = BM * ASTR;           // 4608 floats per A stage
constexpr int B_F = BK * BSTR;           // 8320 floats per B stage
constexpr int SMEM_FLOATS = BM * BSTR;   // 33280 floats (C stage; covers 2A+2B = 25856)
constexpr int SMEM_BYTES  = SMEM_FLOATS * 4;   // 133120

// Mainloop: 128x256 CTA tile, double-buffered cp.async, wmma tf32 m16n16k8.
// arow/brow are per-thread source pointers (already offset to this thread's
// columns). Result tile left in sf[0 .. 128*260) row-major stride BSTR.
template <int NSTG, int BROWSTRIDE>
__device__ __forceinline__ void gemm_core(const float* arow, const float* brow,
                                          float* sf, uint32_t smb, int tid) {
    const int arow_i = tid >> 1;
    const int acol   = (tid & 1) * 16;
    const int brow_i = tid >> 3;
    const int bcol   = (tid & 7) * 32;

    const uint32_t a_dst = smb + (uint32_t)(arow_i * ASTR + acol) * 4u;
    const uint32_t b_dst = smb + (uint32_t)(2 * A_F + brow_i * BSTR + bcol) * 4u;

    auto load_stage = [&](int s, int b) {
        const float* as = arow + s * BK;
        uint32_t ad = a_dst + (uint32_t)(b * A_F) * 4u;
#pragma unroll
        for (int i = 0; i < 4; i++) CP_ASYNC16(ad + i * 16, as + i * 4);
        const float* bs = brow + (size_t)s * BROWSTRIDE;
        uint32_t bd = b_dst + (uint32_t)(b * B_F) * 4u;
#pragma unroll
        for (int i = 0; i < 8; i++) CP_ASYNC16(bd + i * 16, bs + i * 4);
    };

    wmma::fragment<wmma::matrix_a, 16, 16, 8, wmma::precision::tf32, wmma::row_major> af[4];
    wmma::fragment<wmma::matrix_b, 16, 16, 8, wmma::precision::tf32, wmma::row_major> bf[4];
    wmma::fragment<wmma::accumulator, 16, 16, 8, float> cf[4][4];
#pragma unroll
    for (int i = 0; i < 4; i++)
#pragma unroll
        for (int j = 0; j < 4; j++) wmma::fill_fragment(cf[i][j], 0.f);

    const int wid = tid >> 5;
    const int wm  = wid >> 2;   // 0..1  (64-row slabs)
    const int wn  = wid & 3;    // 0..3  (64-col slabs)

    load_stage(0, 0);
    CP_COMMIT();

    for (int s = 0; s < NSTG; s++) {
        if (s + 1 < NSTG) {
            load_stage(s + 1, (s + 1) & 1);
            CP_COMMIT();
            asm volatile("cp.async.wait_group 1;" ::: "memory");
        } else {
            asm volatile("cp.async.wait_group 0;" ::: "memory");
        }
        __syncthreads();

        const float* A = sf + (s & 1) * A_F;
        const float* B = sf + 2 * A_F + (s & 1) * B_F;
#pragma unroll
        for (int kk = 0; kk < BK; kk += 8) {
#pragma unroll
            for (int i = 0; i < 4; i++)
                wmma::load_matrix_sync(af[i], A + (wm * 64 + i * 16) * ASTR + kk, ASTR);
#pragma unroll
            for (int j = 0; j < 4; j++)
                wmma::load_matrix_sync(bf[j], B + kk * BSTR + wn * 64 + j * 16, BSTR);
#pragma unroll
            for (int i = 0; i < 4; i++)
#pragma unroll
                for (int j = 0; j < 4; j++)
                    wmma::mma_sync(cf[i][j], af[i], bf[j], cf[i][j]);
        }
        __syncthreads();
    }

    // park accumulators in smem (C tile 128 x 256, stride BSTR)
#pragma unroll
    for (int i = 0; i < 4; i++)
#pragma unroll
        for (int j = 0; j < 4; j++)
            wmma::store_matrix_sync(sf + (wm * 64 + i * 16) * BSTR + wn * 64 + j * 16,
                                    cf[i][j], BSTR, wmma::mem_row_major);
    __syncthreads();
}

// ============================ GEMM1: H = gelu(X W1 + b1) ===================
__global__ __launch_bounds__(THREADS, 1) void ffn1_tc(const float* __restrict__ b1) {
    int e = blockIdx.z;
    int cnt = g_cnt[e];
    int m0 = blockIdx.y * BM;
    if (m0 >= cnt) return;
    int n0 = blockIdx.x * BN;

    extern __shared__ float sf[];
    uint32_t smb = smem_u32(sf);
    int tid = threadIdx.x;

    // A source: gathered token row (clamp inactive rows to a valid one; masked later)
    int arow_i = tid >> 1;
    int acol   = (tid & 1) * 16;
    int gr = m0 + arow_i;
    int tok = g_tok[e * CAP + (gr < cnt ? gr : cnt - 1)];
    const float* arow = g_xr + (size_t)tok * DMODEL + acol;

    int brow_i = tid >> 3;
    int bcol   = (tid & 7) * 32;
    const float* brow = g_W1r + ((size_t)e * DMODEL + brow_i) * FF + n0 + bcol;

    gemm_core<DMODEL / BK, BK * FF>(arow, brow, sf, smb, tid);

    // epilogue: bias + exact GELU + tf32 round -> g_H
    int row = tid >> 1;
    int cb  = (tid & 1) * 128;
    int gm  = m0 + row;
    if (gm < cnt) {
        const float* bb = b1 + (size_t)e * FF + n0 + cb;
        float* h = g_H + ((size_t)e * CAP + gm) * FF + n0 + cb;
        const float* c = sf + row * BSTR + cb;
#pragma unroll 8
        for (int q = 0; q < 128; q += 4) {
            float4 v;
            v.x = tf32r(gelu_exact(c[q + 0] + bb[q + 0]));
            v.y = tf32r(gelu_exact(c[q + 1] + bb[q + 1]));
            v.z = tf32r(gelu_exact(c[q + 2] + bb[q + 2]));
            v.w = tf32r(gelu_exact(c[q + 3] + bb[q + 3]));
            *reinterpret_cast<float4*>(h + q) = v;
        }
    }
}

// ============================ GEMM2: Y = H W2 + b2 =========================
__global__ __launch_bounds__(THREADS, 1) void ffn2_tc(const float* __restrict__ b2) {
    int e = blockIdx.z;
    int cnt = g_cnt[e];
    int m0 = blockIdx.y * BM;
    if (m0 >= cnt) return;
    int n0 = blockIdx.x * BN;

    extern __shared__ float sf[];
    uint32_t smb = smem_u32(sf);
    int tid = threadIdx.x;

    int arow_i = tid >> 1;
    int acol   = (tid & 1) * 16;
    const float* arow = g_H + ((size_t)e * CAP + m0 + arow_i) * FF + acol; // in-bounds, finite

    int brow_i = tid >> 3;
    int bcol   = (tid & 7) * 32;
    const float* brow = g_W2r + ((size_t)e * FF + brow_i) * DMODEL + n0 + bcol;

    gemm_core<FF / BK, BK * DMODEL>(arow, brow, sf, smb, tid);

    // epilogue: bias -> g_Y (plain stores; combine kernel applies gates)
    int row = tid >> 1;
    int cb  = (tid & 1) * 128;
    int gm  = m0 + row;
    if (gm < cnt) {
        const float* bb = b2 + (size_t)e * DMODEL + n0 + cb;
        float* y = g_Y + ((size_t)e * CAP + gm) * DMODEL + n0 + cb;
        const float* c = sf + row * BSTR + cb;
#pragma unroll 8
        for (int q = 0; q < 128; q += 4) {
            float4 v;
            v.x = c[q + 0] + bb[q + 0];
            v.y = c[q + 1] + bb[q + 1];
            v.z = c[q + 2] + bb[q + 2];
            v.w = c[q + 3] + bb[q + 3];
            *reinterpret_cast<float4*>(y + q) = v;
        }
    }
}

// ============================ combine: out = g1*Y[s1] + g2*Y[s2] ===========
__global__ void combine_kernel(float* __restrict__ out) {
    int i = blockIdx.x * blockDim.x + threadIdx.x;   // over NTOK * DMODEL/4
    if (i >= NTOK * (DMODEL / 4)) return;
    int n  = i >> 8;           // DMODEL/4 == 256
    int c4 = i & 255;
    int   s1 = g_oslot[n * 2 + 0], s2 = g_oslot[n * 2 + 1];
    float g1 = g_ogate[n * 2 + 0], g2 = g_ogate[n * 2 + 1];
    float4 y1 = reinterpret_cast<const float4*>(g_Y + (size_t)s1 * DMODEL)[c4];
    float4 y2 = reinterpret_cast<const float4*>(g_Y + (size_t)s2 * DMODEL)[c4];
    float4 o;
    o.x = g1 * y1.x + g2 * y2.x;
    o.y = g1 * y1.y + g2 * y2.y;
    o.z = g1 * y1.z + g2 * y2.z;
    o.w = g1 * y1.w + g2 * y2.w;
    reinterpret_cast<float4*>(out)[i] = o;
}

// ============================ prep: tf32 round copies ======================
__global__ void round_copy(const float* __restrict__ src, float* __restrict__ dst,
                           int n4, int zero_cnt) {
    int i = blockIdx.x * blockDim.x + threadIdx.x;
    if (i < n4) {
        float4 v = reinterpret_cast<const float4*>(src)[i];
        v.x = tf32r(v.x); v.y = tf32r(v.y); v.z = tf32r(v.z); v.w = tf32r(v.w);
        reinterpret_cast<float4*>(dst)[i] = v;
    }
    if (zero_cnt && i < NE) g_cnt[i] = 0;
}

// ============================ router =======================================
__global__ void router_kernel(const float* __restrict__ x, const float* __restrict__ Wr) {
    int warp = (blockIdx.x * blockDim.x + threadIdx.x) >> 5;
    int lane = threadIdx.x & 31;
    if (warp >= NTOK) return;

    const float* xr = x + (size_t)warp * DMODEL;
    float acc[NE];
#pragma unroll
    for (int e = 0; e < NE; e++) acc[e] = 0.f;
#pragma unroll 4
    for (int i = 0; i < DMODEL / 32; i++) {
        int d = i * 32 + lane;
        float xv = xr[d];
#pragma unroll
        for (int e = 0; e < NE; e++) acc[e] += xv * Wr[e * DMODEL + d];
    }
#pragma unroll
    for (int e = 0; e < NE; e++)
#pragma unroll
        for (int o = 16; o > 0; o >>= 1)
            acc[e] += __shfl_xor_sync(0xffffffffu, acc[e], o);

    if (lane == 0) {
        float m = acc[0];
#pragma unroll
        for (int e = 1; e < NE; e++) m = fmaxf(m, acc[e]);
        float p[NE];
#pragma unroll
        for (int e = 0; e < NE; e++) p[e] = expf(acc[e] - m);
        int i1 = 0;
#pragma unroll
        for (int e = 1; e < NE; e++) if (p[e] > p[i1]) i1 = e;
        int i2 = (i1 == 0) ? 1 : 0;
#pragma unroll
        for (int e = 0; e < NE; e++) {
            if (e == i1) continue;
            if (p[e] > p[i2]) i2 = e;
        }
        float g1 = p[i1], g2 = p[i2];
        float inv = 1.f / (g1 + g2);
        g1 *= inv; g2 *= inv;

        int pos1 = atomicAdd(&g_cnt[i1], 1);
        g_tok[i1 * CAP + pos1] = warp;
        g_oslot[warp * 2 + 0] = i1 * CAP + pos1;
        g_ogate[warp * 2 + 0] = g1;

        int pos2 = atomicAdd(&g_cnt[i2], 1);
        g_tok[i2 * CAP + pos2] = warp;
        g_oslot[warp * 2 + 1] = i2 * CAP + pos2;
        g_ogate[warp * 2 + 1] = g2;
    }
}

// ============================ launch =======================================
extern "C" void kernel_launch(void* const* d_in, const int* in_sizes, int n_in,
                              void* d_out, int out_size) {
    const float* x  = (const float*)d_in[0];
    const float* Wr = (const float*)d_in[1];
    const float* W1 = (const float*)d_in[2];
    const float* b1 = (const float*)d_in[3];
    const float* W2 = (const float*)d_in[4];
    const float* b2 = (const float*)d_in[5];
    float* out = (float*)d_out;

    cudaFuncSetAttribute(ffn1_tc, cudaFuncAttributeMaxDynamicSharedMemorySize, SMEM_BYTES);
    cudaFuncSetAttribute(ffn2_tc, cudaFuncAttributeMaxDynamicSharedMemorySize, SMEM_BYTES);

    float *pXr = nullptr, *pW1r = nullptr, *pW2r = nullptr;
    cudaGetSymbolAddress((void**)&pXr,  g_xr);
    cudaGetSymbolAddress((void**)&pW1r, g_W1r);
    cudaGetSymbolAddress((void**)&pW2r, g_W2r);

    int nx4 = NTOK * DMODEL / 4;
    int nw4 = NE * DMODEL * FF / 4;
    round_copy<<<(nx4 + 255) / 256, 256>>>(x,  pXr,  nx4, 1);
    round_copy<<<(nw4 + 255) / 256, 256>>>(W1, pW1r, nw4, 0);
    round_copy<<<(nw4 + 255) / 256, 256>>>(W2, pW2r, nw4, 0);

    router_kernel<<<(NTOK * 32) / 256, 256>>>(x, Wr);

    ffn1_tc<<<dim3(FF / BN, CAP / BM, NE), THREADS, SMEM_BYTES>>>(b1);
    ffn2_tc<<<dim3(DMODEL / BN, CAP / BM, NE), THREADS, SMEM_BYTES>>>(b2);

    combine_kernel<<<(NTOK * DMODEL / 4 + 255) / 256, 256>>>(out);
}

// round 6
// speedup vs baseline: 3.1460x; 3.0290x over previous
#include <cuda_runtime.h>
#include <mma.h>
#include <cuda_fp16.h>
#include <cstdint>
#include <cmath>

using namespace nvcuda;

// ============================ problem constants ============================
constexpr int NE     = 8;
constexpr int DMODEL = 1024;
constexpr int FF     = 2048;
constexpr int NTOK   = 8192;   // 4*2048
constexpr int CAP    = 8192;   // per-expert worst-case rows

// ============================ scratch (module-load) ========================
__device__ __half g_xh [(size_t)NTOK * DMODEL];        // fp16 x              (16 MB)
__device__ __half g_W1h[(size_t)NE * DMODEL * FF];     // fp16 W1             (32 MB)
__device__ __half g_W2h[(size_t)NE * FF * DMODEL];     // fp16 W2             (32 MB)
__device__ __half g_Hh [(size_t)NE * CAP * FF];        // fp16 hidden         (256 MB)
__device__ float  g_Y  [(size_t)NE * CAP * DMODEL];    // expert outputs fp32 (256 MB)
__device__ int    g_tok  [NE * CAP];
__device__ int    g_cnt  [NE];                         // zero-init; reset by combine tail
__device__ int    g_oslot[NTOK * 2];
__device__ float  g_ogate[NTOK * 2];

// ============================ helpers ======================================
__device__ __forceinline__ uint32_t smem_u32(const void* p) {
    uint32_t a;
    asm("{ .reg .u64 t; cvta.to.shared.u64 t, %1; cvt.u32.u64 %0, t; }" : "=r"(a) : "l"(p));
    return a;
}
#define CP_ASYNC16(dst, src) \
    asm volatile("cp.async.cg.shared.global [%0], [%1], 16;" :: "r"(dst), "l"(src) : "memory")
#define CP_COMMIT()  asm volatile("cp.async.commit_group;" ::: "memory")

__device__ __forceinline__ float gelu_exact(float v) {
    return 0.5f * v * (1.0f + erff(v * 0.70710678118654752f));
}

// ============================ GEMM config ==================================
constexpr int BM = 128;
constexpr int BN = 256;
constexpr int BK = 32;
constexpr int PIPE = 3;
constexpr int THREADS = 256;
constexpr int ASTR = 40;                    // A smem stride (halves) = 80B  (conflict-free LDSM)
constexpr int BSTR = 264;                   // B smem stride (halves) = 528B (conflict-free LDSM)
constexpr int A_HV = BM * ASTR;             // 5120 halves
constexpr int B_HV = BK * BSTR;             // 8448 halves
constexpr int ST_HV = A_HV + B_HV;          // 13568 halves = 27136 B per stage
constexpr int SMEM_BYTES = PIPE * ST_HV * 2;   // 81408 B

using FragC = wmma::fragment<wmma::accumulator, 16, 16, 16, float>;

// Mainloop: 128x256x32 CTA tile, 3-stage cp.async, wmma m16n16k16 half.
// arow/brow: per-thread source pointers already offset to this thread's columns.
template <int NSTG, int BROWSTEP>
__device__ __forceinline__ void gemm_core(const __half* arow, const __half* brow,
                                          __half* sh, int tid, FragC (&cf)[4][4]) {
    uint32_t smb = smem_u32(sh);
    const int ar = tid >> 1;           // 0..127  (A row)
    const int ac = (tid & 1) * 16;     // halves
    const int br = tid >> 3;           // 0..31   (B row)
    const int bc = (tid & 7) * 32;     // halves
    const uint32_t a_dst = smb + (uint32_t)(ar * ASTR + ac) * 2u;
    const uint32_t b_dst = smb + (uint32_t)(A_HV + br * BSTR + bc) * 2u;

    auto load_stage = [&](int s) {
        int b = s % PIPE;
        uint32_t so = (uint32_t)(b * ST_HV) * 2u;
        const __half* as = arow + s * BK;
        CP_ASYNC16(a_dst + so,      as);
        CP_ASYNC16(a_dst + so + 16, as + 8);
        const __half* bs = brow + (size_t)s * BROWSTEP;
        uint32_t bd = b_dst + so;
#pragma unroll
        for (int i = 0; i < 4; i++) CP_ASYNC16(bd + i * 16, bs + i * 8);
    };

    const int wid = tid >> 5;
    const int wm  = wid >> 2;   // 0..1 (64-row slab)
    const int wn  = wid & 3;    // 0..3 (64-col slab)

#pragma unroll
    for (int i = 0; i < 4; i++)
#pragma unroll
        for (int j = 0; j < 4; j++) wmma::fill_fragment(cf[i][j], 0.f);

#pragma unroll
    for (int p = 0; p < PIPE - 1; p++) { load_stage(p); CP_COMMIT(); }

    for (int s = 0; s < NSTG; s++) {
        if (s + 1 < NSTG) asm volatile("cp.async.wait_group 1;" ::: "memory");
        else              asm volatile("cp.async.wait_group 0;" ::: "memory");
        __syncthreads();
        if (s + 2 < NSTG) { load_stage(s + 2); CP_COMMIT(); }

        const __half* A = sh + (s % PIPE) * ST_HV;
        const __half* B = A + A_HV;
        wmma::fragment<wmma::matrix_a, 16, 16, 16, __half, wmma::row_major> af;
        wmma::fragment<wmma::matrix_b, 16, 16, 16, __half, wmma::row_major> bf[4];
#pragma unroll
        for (int kk = 0; kk < BK; kk += 16) {
#pragma unroll
            for (int j = 0; j < 4; j++)
                wmma::load_matrix_sync(bf[j], B + kk * BSTR + wn * 64 + j * 16, BSTR);
#pragma unroll
            for (int i = 0; i < 4; i++) {
                wmma::load_matrix_sync(af, A + (wm * 64 + i * 16) * ASTR + kk, ASTR);
#pragma unroll
                for (int j = 0; j < 4; j++) wmma::mma_sync(cf[i][j], af, bf[j], cf[i][j]);
            }
        }
        // next iteration's wait_group + __syncthreads covers buffer reuse
    }
    __syncthreads();   // smem about to be reused for epilogue staging
}

// ============================ GEMM1: H = gelu(X W1 + b1) ===================
__global__ __launch_bounds__(THREADS, 1) void ffn1_tc(const float* __restrict__ b1) {
    int e = blockIdx.z;
    int cnt = g_cnt[e];
    int m0 = blockIdx.y * BM;
    if (m0 >= cnt) return;
    int n0 = blockIdx.x * BN;

    extern __shared__ __align__(16) char smem[];
    __half* sh = (__half*)smem;
    int tid = threadIdx.x, wid = tid >> 5, lane = tid & 31;
    int wm = wid >> 2, wn = wid & 3;

    // A gather: clamp inactive rows to a valid slot (masked in epilogue)
    int ar = tid >> 1, ac = (tid & 1) * 16;
    int gr = m0 + ar;
    int tok = g_tok[e * CAP + (gr < cnt ? gr : cnt - 1)];
    const __half* arow = g_xh + (size_t)tok * DMODEL + ac;

    int br = tid >> 3, bc = (tid & 7) * 32;
    const __half* brow = g_W1h + ((size_t)e * DMODEL + br) * FF + n0 + bc;

    FragC cf[4][4];
    gemm_core<DMODEL / BK, BK * FF>(arow, brow, sh, tid, cf);

    // epilogue: bias + exact GELU -> fp16 H (stage each 16x16 frag via smem)
    float* cw = (float*)smem + wid * 320;   // 16 x 20 fp32, per warp
    const float* bb = b1 + (size_t)e * FF;
#pragma unroll
    for (int i = 0; i < 4; i++) {
#pragma unroll
        for (int j = 0; j < 4; j++) {
            wmma::store_matrix_sync(cw, cf[i][j], 20, wmma::mem_row_major);
            __syncwarp();
            int gmb = m0 + wm * 64 + i * 16;
            int gnb = n0 + wn * 64 + j * 16;
#pragma unroll
            for (int q = 0; q < 4; q++) {
                int idx = lane * 4 + q;          // 0..127
                int r = idx >> 3, c = (idx & 7) * 2;
                int gm = gmb + r;
                if (gm < cnt) {
                    int gn = gnb + c;
                    float v0 = gelu_exact(cw[r * 20 + c]     + bb[gn]);
                    float v1 = gelu_exact(cw[r * 20 + c + 1] + bb[gn + 1]);
                    *(__half2*)(g_Hh + ((size_t)e * CAP + gm) * FF + gn) =
                        __floats2half2_rn(v0, v1);
                }
            }
            __syncwarp();
        }
    }
}

// ============================ GEMM2: Y = H W2 + b2 =========================
__global__ __launch_bounds__(THREADS, 1) void ffn2_tc(const float* __restrict__ b2) {
    int e = blockIdx.z;
    int cnt = g_cnt[e];
    int m0 = blockIdx.y * BM;
    if (m0 >= cnt) return;
    int n0 = blockIdx.x * BN;

    extern __shared__ __align__(16) char smem[];
    __half* sh = (__half*)smem;
    int tid = threadIdx.x, wid = tid >> 5, lane = tid & 31;
    int wm = wid >> 2, wn = wid & 3;

    int ar = tid >> 1, ac = (tid & 1) * 16;
    const __half* arow = g_Hh + ((size_t)e * CAP + m0 + ar) * FF + ac;  // in-bounds, finite

    int br = tid >> 3, bc = (tid & 7) * 32;
    const __half* brow = g_W2h + ((size_t)e * FF + br) * DMODEL + n0 + bc;

    FragC cf[4][4];
    gemm_core<FF / BK, BK * DMODEL>(arow, brow, sh, tid, cf);

    float* cw = (float*)smem + wid * 320;
    const float* bb = b2 + (size_t)e * DMODEL;
#pragma unroll
    for (int i = 0; i < 4; i++) {
#pragma unroll
        for (int j = 0; j < 4; j++) {
            wmma::store_matrix_sync(cw, cf[i][j], 20, wmma::mem_row_major);
            __syncwarp();
            int gmb = m0 + wm * 64 + i * 16;
            int gnb = n0 + wn * 64 + j * 16;
#pragma unroll
            for (int q = 0; q < 4; q++) {
                int idx = lane * 4 + q;
                int r = idx >> 3, c = (idx & 7) * 2;
                int gm = gmb + r;
                if (gm < cnt) {
                    int gn = gnb + c;
                    float2 v;
                    v.x = cw[r * 20 + c]     + bb[gn];
                    v.y = cw[r * 20 + c + 1] + bb[gn + 1];
                    *(float2*)(g_Y + ((size_t)e * CAP + gm) * DMODEL + gn) = v;
                }
            }
            __syncwarp();
        }
    }
}

// ============================ combine + counter reset ======================
__global__ void combine_kernel(float* __restrict__ out) {
    int i = blockIdx.x * blockDim.x + threadIdx.x;   // over NTOK * DMODEL/4
    if (i < NTOK * (DMODEL / 4)) {
        int n  = i >> 8;            // DMODEL/4 == 256
        int c4 = i & 255;
        int   s1 = g_oslot[n * 2 + 0], s2 = g_oslot[n * 2 + 1];
        float g1 = g_ogate[n * 2 + 0], g2 = g_ogate[n * 2 + 1];
        float4 y1 = reinterpret_cast<const float4*>(g_Y + (size_t)s1 * DMODEL)[c4];
        float4 y2 = reinterpret_cast<const float4*>(g_Y + (size_t)s2 * DMODEL)[c4];
        float4 o;
        o.x = g1 * y1.x + g2 * y2.x;
        o.y = g1 * y1.y + g2 * y2.y;
        o.z = g1 * y1.z + g2 * y2.z;
        o.w = g1 * y1.w + g2 * y2.w;
        reinterpret_cast<float4*>(out)[i] = o;
    }
    if (blockIdx.x == 0 && threadIdx.x < NE) g_cnt[threadIdx.x] = 0;  // ready next call
}

// ============================ fp32 -> fp16 conversion ======================
__global__ void conv2(const float* __restrict__ s1, __half* __restrict__ d1, int n1,
                      const float* __restrict__ s2, __half* __restrict__ d2, int n2) {
    int i = blockIdx.x * blockDim.x + threadIdx.x;   // float4 units
    const float* s; __half* d; int k;
    if (i < n1)            { s = s1; d = d1; k = i; }
    else if (i < n1 + n2)  { s = s2; d = d2; k = i - n1; }
    else return;
    float4 v = reinterpret_cast<const float4*>(s)[k];
    __half2* dp = reinterpret_cast<__half2*>(d);
    dp[k * 2]     = __floats2half2_rn(v.x, v.y);
    dp[k * 2 + 1] = __floats2half2_rn(v.z, v.w);
}

// ============================ router =======================================
__global__ void router_kernel(const float* __restrict__ x, const float* __restrict__ Wr) {
    int warp = (blockIdx.x * blockDim.x + threadIdx.x) >> 5;
    int lane = threadIdx.x & 31;
    if (warp >= NTOK) return;

    const float* xr = x + (size_t)warp * DMODEL;
    float acc[NE];
#pragma unroll
    for (int e = 0; e < NE; e++) acc[e] = 0.f;
#pragma unroll 4
    for (int i = 0; i < DMODEL / 32; i++) {
        int d = i * 32 + lane;
        float xv = xr[d];
#pragma unroll
        for (int e = 0; e < NE; e++) acc[e] += xv * Wr[e * DMODEL + d];
    }
#pragma unroll
    for (int e = 0; e < NE; e++)
#pragma unroll
        for (int o = 16; o > 0; o >>= 1)
            acc[e] += __shfl_xor_sync(0xffffffffu, acc[e], o);

    if (lane == 0) {
        float m = acc[0];
#pragma unroll
        for (int e = 1; e < NE; e++) m = fmaxf(m, acc[e]);
        float p[NE];
#pragma unroll
        for (int e = 0; e < NE; e++) p[e] = expf(acc[e] - m);
        int i1 = 0;
#pragma unroll
        for (int e = 1; e < NE; e++) if (p[e] > p[i1]) i1 = e;
        int i2 = (i1 == 0) ? 1 : 0;
#pragma unroll
        for (int e = 0; e < NE; e++) {
            if (e == i1) continue;
            if (p[e] > p[i2]) i2 = e;
        }
        float g1 = p[i1], g2 = p[i2];
        float inv = 1.f / (g1 + g2);
        g1 *= inv; g2 *= inv;

        int pos1 = atomicAdd(&g_cnt[i1], 1);
        g_tok[i1 * CAP + pos1] = warp;
        g_oslot[warp * 2 + 0] = i1 * CAP + pos1;
        g_ogate[warp * 2 + 0] = g1;

        int pos2 = atomicAdd(&g_cnt[i2], 1);
        g_tok[i2 * CAP + pos2] = warp;
        g_oslot[warp * 2 + 1] = i2 * CAP + pos2;
        g_ogate[warp * 2 + 1] = g2;
    }
}

// ============================ launch =======================================
extern "C" void kernel_launch(void* const* d_in, const int* in_sizes, int n_in,
                              void* d_out, int out_size) {
    const float* x  = (const float*)d_in[0];
    const float* Wr = (const float*)d_in[1];
    const float* W1 = (const float*)d_in[2];
    const float* b1 = (const float*)d_in[3];
    const float* W2 = (const float*)d_in[4];
    const float* b2 = (const float*)d_in[5];
    float* out = (float*)d_out;

    cudaFuncSetAttribute(ffn1_tc, cudaFuncAttributeMaxDynamicSharedMemorySize, SMEM_BYTES);
    cudaFuncSetAttribute(ffn2_tc, cudaFuncAttributeMaxDynamicSharedMemorySize, SMEM_BYTES);

    __half *pXh = nullptr, *pW1h = nullptr, *pW2h = nullptr;
    cudaGetSymbolAddress((void**)&pXh,  g_xh);
    cudaGetSymbolAddress((void**)&pW1h, g_W1h);
    cudaGetSymbolAddress((void**)&pW2h, g_W2h);

    int nx4 = NTOK * DMODEL / 4;             // 2M
    int nw4 = NE * DMODEL * FF / 4;          // 4M

    // Launch order keeps ffn1 as kernel launch #4 (the one ncu captures).
    router_kernel<<<(NTOK * 32) / 256, 256>>>(x, Wr);                     // 1
    conv2<<<(nx4 + nw4 + 255) / 256, 256>>>(x, pXh, nx4, W1, pW1h, nw4);  // 2
    conv2<<<(nw4 + 255) / 256, 256>>>(W2, pW2h, nw4, W2, pW2h, 0);        // 3
    ffn1_tc<<<dim3(FF / BN, CAP / BM, NE), THREADS, SMEM_BYTES>>>(b1);    // 4
    ffn2_tc<<<dim3(DMODEL / BN, CAP / BM, NE), THREADS, SMEM_BYTES>>>(b2);// 5
    combine_kernel<<<(NTOK * DMODEL / 4 + 255) / 256, 256>>>(out);        // 6
}